// round 2
// baseline (speedup 1.0000x reference)
#include <cuda_runtime.h>
#include <math.h>

#define H_ 16
#define DM 1024
#define DK 64
#define BB 4
#define SS 2048
#define NR (BB*SS)   // 8192 rows

// ---------------- scratch (device globals; allocation-free) ----------------
__device__ float g_Q[(size_t)BB*H_*SS*DK];   // head-major Q
__device__ float g_K[(size_t)BB*H_*SS*DK];
__device__ float g_V[(size_t)BB*H_*SS*DK];
__device__ float g_X[(size_t)NR*DM];         // attention output, flat (B,S,DM)
__device__ float g_Y[(size_t)NR*DM];         // pre-LN (proj + bias + residual)

// ---------------- GEMM: out = A(8192x1024) @ W(1024x1024)^T + bias ----------
// mode 0: write head-major into out (h = blockIdx.x since tile width == DK)
// mode 1: write flat, adding residual
__global__ __launch_bounds__(256) void gemm64(
    const float* __restrict__ A,
    const float* __restrict__ W,
    const float* __restrict__ bias,
    const float* __restrict__ residual,
    float* __restrict__ out,
    int mode)
{
    const int bx = blockIdx.x;      // col tile: 16
    const int by = blockIdx.y;      // row tile: 128
    const int tid = threadIdx.x;
    const int tx = tid & 15, ty = tid >> 4;

    __shared__ float As[16][64];
    __shared__ float Bs[16][64];

    const int row0 = by * 64, col0 = bx * 64;
    const int lr = tid >> 2;          // 0..63
    const int lk = (tid & 3) << 2;    // 0,4,8,12

    float acc[4][4] = {};

    for (int kk = 0; kk < DM; kk += 16) {
        float4 av = *reinterpret_cast<const float4*>(&A[(size_t)(row0 + lr) * DM + kk + lk]);
        float4 bv = *reinterpret_cast<const float4*>(&W[(size_t)(col0 + lr) * DM + kk + lk]);
        As[lk + 0][lr] = av.x; As[lk + 1][lr] = av.y;
        As[lk + 2][lr] = av.z; As[lk + 3][lr] = av.w;
        Bs[lk + 0][lr] = bv.x; Bs[lk + 1][lr] = bv.y;
        Bs[lk + 2][lr] = bv.z; Bs[lk + 3][lr] = bv.w;
        __syncthreads();

        #pragma unroll
        for (int k = 0; k < 16; ++k) {
            float4 a = *reinterpret_cast<const float4*>(&As[k][ty * 4]);
            float4 b = *reinterpret_cast<const float4*>(&Bs[k][tx * 4]);
            float aa[4] = {a.x, a.y, a.z, a.w};
            float bb[4] = {b.x, b.y, b.z, b.w};
            #pragma unroll
            for (int i = 0; i < 4; ++i)
                #pragma unroll
                for (int j = 0; j < 4; ++j)
                    acc[i][j] += aa[i] * bb[j];
        }
        __syncthreads();
    }

    float4 bv4 = *reinterpret_cast<const float4*>(&bias[col0 + tx * 4]);
    float bb[4] = {bv4.x, bv4.y, bv4.z, bv4.w};

    if (mode == 0) {
        // head-major: dk = tx*4+j, h = bx, row n -> (b,s)
        #pragma unroll
        for (int i = 0; i < 4; ++i) {
            int n = row0 + ty * 4 + i;
            int b_ = n >> 11;          // /2048
            int s_ = n & 2047;
            size_t base = (((size_t)b_ * H_ + bx) * SS + s_) * DK + tx * 4;
            float4 ov;
            ov.x = acc[i][0] + bb[0]; ov.y = acc[i][1] + bb[1];
            ov.z = acc[i][2] + bb[2]; ov.w = acc[i][3] + bb[3];
            *reinterpret_cast<float4*>(&out[base]) = ov;
        }
    } else {
        #pragma unroll
        for (int i = 0; i < 4; ++i) {
            int n = row0 + ty * 4 + i;
            size_t base = (size_t)n * DM + col0 + tx * 4;
            float4 rv = *reinterpret_cast<const float4*>(&residual[base]);
            float4 ov;
            ov.x = acc[i][0] + bb[0] + rv.x; ov.y = acc[i][1] + bb[1] + rv.y;
            ov.z = acc[i][2] + bb[2] + rv.z; ov.w = acc[i][3] + bb[3] + rv.w;
            *reinterpret_cast<float4*>(&out[base]) = ov;
        }
    }
}

// ---------------- Flash attention, fp32, BQ=64, BKV=32 ---------------------
// grid: (SS/64, BB*H_), block 256 = (tx 0..15, ty 0..15)
// thread owns rows ty*4+i. Scores: cols tx*2+jj. Output: cols tx*4+j.
__global__ __launch_bounds__(256) void attn_kernel()
{
    const int bh = blockIdx.y;
    const int b = bh >> 4, h = bh & 15;
    const int q0 = blockIdx.x * 64;
    const int tid = threadIdx.x;
    const int tx = tid & 15, ty = tid >> 4;

    const float* Qp = g_Q + (size_t)bh * SS * DK;
    const float* Kp = g_K + (size_t)bh * SS * DK;
    const float* Vp = g_V + (size_t)bh * SS * DK;

    __shared__ float Qs[64 * 64];     // stride 64
    __shared__ float KPs[2112];       // union: K tile [32][65] / P tile [64][33]
    __shared__ float Vs[32 * 64];     // stride 64

    // load Q tile (64x64)
    for (int i = tid; i < 64 * 16; i += 256) {
        int r = i >> 4, c4 = (i & 15) << 2;
        *reinterpret_cast<float4*>(&Qs[r * 64 + c4]) =
            *reinterpret_cast<const float4*>(&Qp[(size_t)(q0 + r) * DK + c4]);
    }

    float o[4][4] = {};
    float m_i[4], l_i[4];
    #pragma unroll
    for (int i = 0; i < 4; ++i) { m_i[i] = -1e30f; l_i[i] = 0.f; }

    for (int kv0 = 0; kv0 < SS; kv0 += 32) {
        __syncthreads();  // previous-iter smem reads done (also covers Q load, iter 0)

        // load K (stride 65) + V (stride 64) tiles: 32x64 each
        for (int i = tid; i < 512; i += 256) {
            int r = i >> 4, c4 = (i & 15) << 2;
            float4 k4 = *reinterpret_cast<const float4*>(&Kp[(size_t)(kv0 + r) * DK + c4]);
            KPs[r * 65 + c4 + 0] = k4.x; KPs[r * 65 + c4 + 1] = k4.y;
            KPs[r * 65 + c4 + 2] = k4.z; KPs[r * 65 + c4 + 3] = k4.w;
            *reinterpret_cast<float4*>(&Vs[r * 64 + c4]) =
                *reinterpret_cast<const float4*>(&Vp[(size_t)(kv0 + r) * DK + c4]);
        }
        __syncthreads();

        // scores: s[i][jj] = Q[row] . K[col]
        float s[4][2] = {};
        const int c0 = tx * 2;
        #pragma unroll 8
        for (int d = 0; d < 64; ++d) {
            float b0 = KPs[(c0 + 0) * 65 + d];
            float b1 = KPs[(c0 + 1) * 65 + d];
            #pragma unroll
            for (int i = 0; i < 4; ++i) {
                float a = Qs[(ty * 4 + i) * 64 + d];
                s[i][0] += a * b0;
                s[i][1] += a * b1;
            }
        }

        float p[4][2];
        float mnew[4], alpha[4], rs[4];
        #pragma unroll
        for (int i = 0; i < 4; ++i) {
            s[i][0] *= 0.125f; s[i][1] *= 0.125f;   // 1/sqrt(64)
            float mt = fmaxf(s[i][0], s[i][1]);
            #pragma unroll
            for (int off = 8; off >= 1; off >>= 1)
                mt = fmaxf(mt, __shfl_xor_sync(0xffffffffu, mt, off));
            mnew[i] = fmaxf(m_i[i], mt);
            alpha[i] = __expf(m_i[i] - mnew[i]);
            p[i][0] = __expf(s[i][0] - mnew[i]);
            p[i][1] = __expf(s[i][1] - mnew[i]);
            float r = p[i][0] + p[i][1];
            #pragma unroll
            for (int off = 8; off >= 1; off >>= 1)
                r += __shfl_xor_sync(0xffffffffu, r, off);
            rs[i] = r;
        }
        #pragma unroll
        for (int i = 0; i < 4; ++i) {
            l_i[i] = l_i[i] * alpha[i] + rs[i];
            m_i[i] = mnew[i];
            #pragma unroll
            for (int j = 0; j < 4; ++j) o[i][j] *= alpha[i];
        }

        __syncthreads();  // K reads finished -> safe to overwrite as P

        #pragma unroll
        for (int i = 0; i < 4; ++i) {
            KPs[(ty * 4 + i) * 33 + c0 + 0] = p[i][0];
            KPs[(ty * 4 + i) * 33 + c0 + 1] = p[i][1];
        }
        __syncthreads();

        // O += P @ V : per k, 1 float4 V load + 4 P loads -> 16 FMA
        const int vc = tx * 4;
        #pragma unroll 8
        for (int k = 0; k < 32; ++k) {
            float4 v = *reinterpret_cast<const float4*>(&Vs[k * 64 + vc]);
            #pragma unroll
            for (int i = 0; i < 4; ++i) {
                float pr = KPs[(ty * 4 + i) * 33 + k];
                o[i][0] += pr * v.x; o[i][1] += pr * v.y;
                o[i][2] += pr * v.z; o[i][3] += pr * v.w;
            }
        }
    }

    // normalize + write to flat X layout (B,S,DM)
    #pragma unroll
    for (int i = 0; i < 4; ++i) {
        int srow = q0 + ty * 4 + i;
        float inv = 1.f / l_i[i];
        float4 ov;
        ov.x = o[i][0] * inv; ov.y = o[i][1] * inv;
        ov.z = o[i][2] * inv; ov.w = o[i][3] * inv;
        size_t base = ((size_t)(b * SS + srow)) * DM + h * DK + tx * 4;
        *reinterpret_cast<float4*>(&g_X[base]) = ov;
    }
}

// ---------------- LayerNorm over rows of 1024 -------------------------------
__global__ __launch_bounds__(256) void ln_kernel(
    const float* __restrict__ Y,
    const float* __restrict__ gam,
    const float* __restrict__ bet,
    float* __restrict__ out)
{
    int row = blockIdx.x;
    const float* y = Y + (size_t)row * DM;
    int c = threadIdx.x * 4;
    float4 v = *reinterpret_cast<const float4*>(&y[c]);
    float s  = v.x + v.y + v.z + v.w;
    float sq = v.x * v.x + v.y * v.y + v.z * v.z + v.w * v.w;

    #pragma unroll
    for (int off = 16; off >= 1; off >>= 1) {
        s  += __shfl_xor_sync(0xffffffffu, s,  off);
        sq += __shfl_xor_sync(0xffffffffu, sq, off);
    }
    __shared__ float sh[16];
    int w = threadIdx.x >> 5, ln = threadIdx.x & 31;
    if (ln == 0) { sh[w] = s; sh[w + 8] = sq; }
    __syncthreads();
    if (threadIdx.x < 32) {
        float a  = (threadIdx.x < 8) ? sh[threadIdx.x] : 0.f;
        float b2 = (threadIdx.x < 8) ? sh[threadIdx.x + 8] : 0.f;
        #pragma unroll
        for (int off = 4; off >= 1; off >>= 1) {
            a  += __shfl_xor_sync(0xffffffffu, a,  off);
            b2 += __shfl_xor_sync(0xffffffffu, b2, off);
        }
        if (threadIdx.x == 0) { sh[0] = a; sh[1] = b2; }
    }
    __syncthreads();
    float mu  = sh[0] * (1.f / 1024.f);
    float var = sh[1] * (1.f / 1024.f) - mu * mu;
    float r = rsqrtf(var + 1e-5f);

    float4 gv = *reinterpret_cast<const float4*>(&gam[c]);
    float4 bv = *reinterpret_cast<const float4*>(&bet[c]);
    float4 ov;
    ov.x = (v.x - mu) * r * gv.x + bv.x;
    ov.y = (v.y - mu) * r * gv.y + bv.y;
    ov.z = (v.z - mu) * r * gv.z + bv.z;
    ov.w = (v.w - mu) * r * gv.w + bv.w;
    *reinterpret_cast<float4*>(&out[(size_t)row * DM + c]) = ov;
}

// ---------------- launch ----------------------------------------------------
extern "C" void kernel_launch(void* const* d_in, const int* in_sizes, int n_in,
                              void* d_out, int out_size)
{
    const float* q    = (const float*)d_in[0];
    const float* k    = (const float*)d_in[1];
    const float* v    = (const float*)d_in[2];
    const float* Wq   = (const float*)d_in[3];
    const float* bq   = (const float*)d_in[4];
    const float* Wk   = (const float*)d_in[5];
    const float* bk   = (const float*)d_in[6];
    const float* Wv   = (const float*)d_in[7];
    const float* bv   = (const float*)d_in[8];
    const float* Wo   = (const float*)d_in[9];
    const float* bo   = (const float*)d_in[10];
    const float* ln_g = (const float*)d_in[11];
    const float* ln_b = (const float*)d_in[12];
    float* out = (float*)d_out;

    float *pQ, *pK, *pV, *pX, *pY;
    cudaGetSymbolAddress((void**)&pQ, g_Q);
    cudaGetSymbolAddress((void**)&pK, g_K);
    cudaGetSymbolAddress((void**)&pV, g_V);
    cudaGetSymbolAddress((void**)&pX, g_X);
    cudaGetSymbolAddress((void**)&pY, g_Y);

    dim3 gg(DM / 64, NR / 64);   // (16, 128)
    gemm64<<<gg, 256>>>(q, Wq, bq, nullptr, pQ, 0);
    gemm64<<<gg, 256>>>(k, Wk, bk, nullptr, pK, 0);
    gemm64<<<gg, 256>>>(v, Wv, bv, nullptr, pV, 0);

    dim3 ga(SS / 64, BB * H_);   // (32, 64)
    attn_kernel<<<ga, 256>>>();

    gemm64<<<gg, 256>>>(pX, Wo, bo, q, pY, 1);

    ln_kernel<<<NR, 256>>>(pY, ln_g, ln_b, out);
}

// round 4
// speedup vs baseline: 3.5307x; 3.5307x over previous
#include <cuda_runtime.h>
#include <math.h>
#include <stdint.h>

#define H_ 16
#define DM 1024
#define DK 64
#define BB 4
#define SS 2048
#define NR (BB*SS)   // 8192 rows

// ---------------- scratch (device globals; allocation-free) ----------------
__device__ float g_Q[(size_t)BB*H_*SS*DK];   // head-major Q
__device__ float g_K[(size_t)BB*H_*SS*DK];
__device__ float g_V[(size_t)BB*H_*SS*DK];
__device__ float g_X[(size_t)NR*DM];         // attention output, flat (B,S,DM)
__device__ float g_Y[(size_t)NR*DM];         // pre-LN (proj + bias + residual)

// ---------------- helpers ---------------------------------------------------
__device__ __forceinline__ uint32_t tf32_of(float x) {
    uint32_t r; asm("cvt.rna.tf32.f32 %0, %1;" : "=r"(r) : "f"(x)); return r;
}
__device__ __forceinline__ float tf32f(float x) {
    return __uint_as_float(tf32_of(x));
}
__device__ __forceinline__ void cp16(uint32_t smem, const void* gmem) {
    asm volatile("cp.async.ca.shared.global [%0], [%1], 16;" :: "r"(smem), "l"(gmem));
}
__device__ __forceinline__ void mma_tf32(float* c, const uint32_t* a, const uint32_t* b) {
    asm volatile(
        "mma.sync.aligned.m16n8k8.row.col.f32.tf32.tf32.f32 "
        "{%0,%1,%2,%3}, {%4,%5,%6,%7}, {%8,%9}, {%0,%1,%2,%3};"
        : "+f"(c[0]), "+f"(c[1]), "+f"(c[2]), "+f"(c[3])
        : "r"(a[0]), "r"(a[1]), "r"(a[2]), "r"(a[3]), "r"(b[0]), "r"(b[1]));
}

// ---------------- tf32 GEMM: out = A(8192x1024) @ W(1024x1024)^T + bias -----
// BM=128 BN=128 BK=32, 256 threads, 8 warps (2M x 4N), warp tile 64x32.
// smem stride 36 (== 4 mod 32) -> all fragment LDS conflict-free.
// mode 0: head-major QKV write;  mode 1: flat write + residual.
#define GST 36

__global__ __launch_bounds__(256) void gemm_tf32(
    const float* __restrict__ A,
    const float* __restrict__ W,
    const float* __restrict__ bias,
    const float* __restrict__ residual,
    float* __restrict__ out,
    int mode)
{
    extern __shared__ __align__(16) float gsm[];
    float* As = gsm;                    // [2][128*36]
    float* Bs = gsm + 2 * 128 * GST;    // [2][128*36]

    const int tid = threadIdx.x;
    const int warp = tid >> 5, lane = tid & 31;
    const int wm = warp >> 2, wn = warp & 3;
    const int g = lane >> 2, tg = lane & 3;
    const int row0 = blockIdx.y * 128, col0 = blockIdx.x * 128;

    float acc[4][4][4];
    #pragma unroll
    for (int i = 0; i < 4; ++i)
        #pragma unroll
        for (int j = 0; j < 4; ++j)
            #pragma unroll
            for (int r = 0; r < 4; ++r) acc[i][j][r] = 0.f;

    const uint32_t sA = (uint32_t)__cvta_generic_to_shared(As);
    const uint32_t sB = (uint32_t)__cvta_generic_to_shared(Bs);

    auto issue_tile = [&](int kt, int buf) {
        const float* Ag = A + (size_t)row0 * DM + kt * 32;
        const float* Wg = W + (size_t)col0 * DM + kt * 32;
        uint32_t dstA = sA + (uint32_t)(buf * 128 * GST) * 4;
        uint32_t dstB = sB + (uint32_t)(buf * 128 * GST) * 4;
        #pragma unroll
        for (int v = 0; v < 4; ++v) {
            int idx = tid + 256 * v;
            int m = idx >> 3, kk = (idx & 7) * 4;
            cp16(dstA + (uint32_t)(m * GST + kk) * 4, Ag + (size_t)m * DM + kk);
            cp16(dstB + (uint32_t)(m * GST + kk) * 4, Wg + (size_t)m * DM + kk);
        }
        asm volatile("cp.async.commit_group;");
    };

    issue_tile(0, 0);

    for (int kt = 0; kt < 32; ++kt) {
        int buf = kt & 1;
        if (kt + 1 < 32) {
            issue_tile(kt + 1, buf ^ 1);
            asm volatile("cp.async.wait_group 1;");
        } else {
            asm volatile("cp.async.wait_group 0;");
        }
        __syncthreads();

        const float* as = As + buf * 128 * GST;
        const float* bs = Bs + buf * 128 * GST;

        #pragma unroll
        for (int ks = 0; ks < 4; ++ks) {
            uint32_t af[4][4], bf[4][2];
            #pragma unroll
            for (int mi = 0; mi < 4; ++mi) {
                const float* p = as + (wm * 64 + mi * 16 + g) * GST + ks * 8 + tg;
                af[mi][0] = tf32_of(p[0]);
                af[mi][1] = tf32_of(p[8 * GST]);
                af[mi][2] = tf32_of(p[4]);
                af[mi][3] = tf32_of(p[8 * GST + 4]);
            }
            #pragma unroll
            for (int ni = 0; ni < 4; ++ni) {
                const float* p = bs + (wn * 32 + ni * 8 + g) * GST + ks * 8 + tg;
                bf[ni][0] = tf32_of(p[0]);
                bf[ni][1] = tf32_of(p[4]);
            }
            #pragma unroll
            for (int mi = 0; mi < 4; ++mi)
                #pragma unroll
                for (int ni = 0; ni < 4; ++ni)
                    mma_tf32(acc[mi][ni], af[mi], bf[ni]);
        }
        __syncthreads();
    }

    // epilogue
    #pragma unroll
    for (int mi = 0; mi < 4; ++mi) {
        int r0 = row0 + wm * 64 + mi * 16 + g;
        int r1 = r0 + 8;
        #pragma unroll
        for (int ni = 0; ni < 4; ++ni) {
            int col = col0 + wn * 32 + ni * 8 + 2 * tg;
            float2 bz = *(const float2*)&bias[col];
            const float* c = acc[mi][ni];
            if (mode == 0) {
                int h = col >> 6, dk = col & 63;
                int b0_ = r0 >> 11, s0_ = r0 & 2047;
                int b1_ = r1 >> 11, s1_ = r1 & 2047;
                size_t base0 = (((size_t)b0_ * H_ + h) * SS + s0_) * DK + dk;
                size_t base1 = (((size_t)b1_ * H_ + h) * SS + s1_) * DK + dk;
                *(float2*)&out[base0] = make_float2(c[0] + bz.x, c[1] + bz.y);
                *(float2*)&out[base1] = make_float2(c[2] + bz.x, c[3] + bz.y);
            } else {
                size_t base0 = (size_t)r0 * DM + col;
                size_t base1 = (size_t)r1 * DM + col;
                float2 rv0 = *(const float2*)&residual[base0];
                float2 rv1 = *(const float2*)&residual[base1];
                *(float2*)&out[base0] = make_float2(c[0] + bz.x + rv0.x, c[1] + bz.y + rv0.y);
                *(float2*)&out[base1] = make_float2(c[2] + bz.x + rv1.x, c[3] + bz.y + rv1.y);
            }
        }
    }
}

// ---------------- tf32 flash attention --------------------------------------
// grid (SS/64, BB*H_), 128 threads (4 warps). Warp owns 16 q-rows.
// BKV=64. Strides: Qs/Ks/Ps 68 (==4 mod 32), Vs 72 (==8 mod 32) -> conflict-free frags.
#define QST 68
#define VST 72

__global__ __launch_bounds__(128) void attn_tc()
{
    extern __shared__ __align__(16) float sm[];
    float* Qs = sm;                          // 64*68
    float* Ks = sm + 64 * QST;               // 64*68
    float* Vs = sm + 2 * 64 * QST;           // 64*72
    float* Ps = sm + 2 * 64 * QST + 64 * VST;// 64*68

    const int bh = blockIdx.y;
    const int b = bh >> 4, h = bh & 15;
    const int q0 = blockIdx.x * 64;
    const int tid = threadIdx.x, warp = tid >> 5, lane = tid & 31;
    const int g = lane >> 2, tg = lane & 3;
    const int qm = warp * 16;

    const float* Qp = g_Q + (size_t)bh * SS * DK + (size_t)q0 * DK;
    const float* Kp = g_K + (size_t)bh * SS * DK;
    const float* Vp = g_V + (size_t)bh * SS * DK;

    // load Q tile, rounding to tf32 at store
    #pragma unroll
    for (int v = 0; v < 8; ++v) {
        int idx = tid + 128 * v;
        int r = idx >> 4, c = (idx & 15) * 4;
        float4 x = *(const float4*)&Qp[(size_t)r * DK + c];
        float* d = &Qs[r * QST + c];
        d[0] = tf32f(x.x); d[1] = tf32f(x.y); d[2] = tf32f(x.z); d[3] = tf32f(x.w);
    }

    float o[8][4];
    #pragma unroll
    for (int i = 0; i < 8; ++i)
        #pragma unroll
        for (int j = 0; j < 4; ++j) o[i][j] = 0.f;
    float m0 = -1e30f, m1 = -1e30f, l0 = 0.f, l1 = 0.f;

    for (int kv0 = 0; kv0 < SS; kv0 += 64) {
        __syncthreads();   // prior-iter smem reads done (covers Q load on iter 0)
        #pragma unroll
        for (int v = 0; v < 8; ++v) {
            int idx = tid + 128 * v;
            int r = idx >> 4, c = (idx & 15) * 4;
            float4 kx = *(const float4*)&Kp[(size_t)(kv0 + r) * DK + c];
            float4 vx = *(const float4*)&Vp[(size_t)(kv0 + r) * DK + c];
            float* dk_ = &Ks[r * QST + c];
            dk_[0] = tf32f(kx.x); dk_[1] = tf32f(kx.y); dk_[2] = tf32f(kx.z); dk_[3] = tf32f(kx.w);
            float* dv = &Vs[r * VST + c];
            dv[0] = tf32f(vx.x); dv[1] = tf32f(vx.y); dv[2] = tf32f(vx.z); dv[3] = tf32f(vx.w);
        }
        __syncthreads();

        // S = Q @ K^T  (16x64 per warp)
        float s[8][4];
        #pragma unroll
        for (int i = 0; i < 8; ++i)
            #pragma unroll
            for (int j = 0; j < 4; ++j) s[i][j] = 0.f;

        #pragma unroll
        for (int ks = 0; ks < 8; ++ks) {
            uint32_t af[4];
            const float* qp_ = &Qs[(qm + g) * QST + ks * 8 + tg];
            af[0] = __float_as_uint(qp_[0]);
            af[1] = __float_as_uint(qp_[8 * QST]);
            af[2] = __float_as_uint(qp_[4]);
            af[3] = __float_as_uint(qp_[8 * QST + 4]);
            #pragma unroll
            for (int nf = 0; nf < 8; ++nf) {
                uint32_t bf[2];
                const float* kp_ = &Ks[(nf * 8 + g) * QST + ks * 8 + tg];
                bf[0] = __float_as_uint(kp_[0]);
                bf[1] = __float_as_uint(kp_[4]);
                mma_tf32(s[nf], af, bf);
            }
        }

        // online softmax (thread rows: qm+g, qm+g+8)
        float mx0 = -1e30f, mx1 = -1e30f;
        #pragma unroll
        for (int nf = 0; nf < 8; ++nf) {
            s[nf][0] *= 0.125f; s[nf][1] *= 0.125f;
            s[nf][2] *= 0.125f; s[nf][3] *= 0.125f;
            mx0 = fmaxf(mx0, fmaxf(s[nf][0], s[nf][1]));
            mx1 = fmaxf(mx1, fmaxf(s[nf][2], s[nf][3]));
        }
        mx0 = fmaxf(mx0, __shfl_xor_sync(0xffffffffu, mx0, 1));
        mx0 = fmaxf(mx0, __shfl_xor_sync(0xffffffffu, mx0, 2));
        mx1 = fmaxf(mx1, __shfl_xor_sync(0xffffffffu, mx1, 1));
        mx1 = fmaxf(mx1, __shfl_xor_sync(0xffffffffu, mx1, 2));

        float nm0 = fmaxf(m0, mx0), nm1 = fmaxf(m1, mx1);
        float a0 = __expf(m0 - nm0), a1 = __expf(m1 - nm1);
        float sum0 = 0.f, sum1 = 0.f;
        #pragma unroll
        for (int nf = 0; nf < 8; ++nf) {
            float p0 = __expf(s[nf][0] - nm0);
            float p1 = __expf(s[nf][1] - nm0);
            float p2 = __expf(s[nf][2] - nm1);
            float p3 = __expf(s[nf][3] - nm1);
            sum0 += p0 + p1; sum1 += p2 + p3;
            float* pp = &Ps[(qm + g) * QST + nf * 8 + 2 * tg];
            pp[0] = tf32f(p0); pp[1] = tf32f(p1);
            pp[8 * QST] = tf32f(p2); pp[8 * QST + 1] = tf32f(p3);
        }
        sum0 += __shfl_xor_sync(0xffffffffu, sum0, 1);
        sum0 += __shfl_xor_sync(0xffffffffu, sum0, 2);
        sum1 += __shfl_xor_sync(0xffffffffu, sum1, 1);
        sum1 += __shfl_xor_sync(0xffffffffu, sum1, 2);

        l0 = l0 * a0 + sum0; l1 = l1 * a1 + sum1;
        m0 = nm0; m1 = nm1;
        #pragma unroll
        for (int df = 0; df < 8; ++df) {
            o[df][0] *= a0; o[df][1] *= a0;
            o[df][2] *= a1; o[df][3] *= a1;
        }
        __syncwarp();

        // O += P @ V  (16x64 per warp)
        #pragma unroll
        for (int ks = 0; ks < 8; ++ks) {
            uint32_t af[4];
            const float* pp = &Ps[(qm + g) * QST + ks * 8 + tg];
            af[0] = __float_as_uint(pp[0]);
            af[1] = __float_as_uint(pp[8 * QST]);
            af[2] = __float_as_uint(pp[4]);
            af[3] = __float_as_uint(pp[8 * QST + 4]);
            #pragma unroll
            for (int df = 0; df < 8; ++df) {
                uint32_t bf[2];
                const float* vp_ = &Vs[(ks * 8 + tg) * VST + df * 8 + g];
                bf[0] = __float_as_uint(vp_[0]);
                bf[1] = __float_as_uint(vp_[4 * VST]);
                mma_tf32(o[df], af, bf);
            }
        }
    }

    // normalize + write flat X layout (B,S,DM)
    float i0 = 1.f / l0, i1 = 1.f / l1;
    int r0g = q0 + qm + g, r1g = r0g + 8;
    #pragma unroll
    for (int df = 0; df < 8; ++df) {
        int d = df * 8 + 2 * tg;
        size_t b0_ = ((size_t)(b * SS + r0g)) * DM + h * DK + d;
        size_t b1_ = ((size_t)(b * SS + r1g)) * DM + h * DK + d;
        *(float2*)&g_X[b0_] = make_float2(o[df][0] * i0, o[df][1] * i0);
        *(float2*)&g_X[b1_] = make_float2(o[df][2] * i1, o[df][3] * i1);
    }
}

// ---------------- LayerNorm over rows of 1024 -------------------------------
__global__ __launch_bounds__(256) void ln_kernel(
    const float* __restrict__ Y,
    const float* __restrict__ gam,
    const float* __restrict__ bet,
    float* __restrict__ out)
{
    int row = blockIdx.x;
    const float* y = Y + (size_t)row * DM;
    int c = threadIdx.x * 4;
    float4 v = *reinterpret_cast<const float4*>(&y[c]);
    float s  = v.x + v.y + v.z + v.w;
    float sq = v.x * v.x + v.y * v.y + v.z * v.z + v.w * v.w;

    #pragma unroll
    for (int off = 16; off >= 1; off >>= 1) {
        s  += __shfl_xor_sync(0xffffffffu, s,  off);
        sq += __shfl_xor_sync(0xffffffffu, sq, off);
    }
    __shared__ float sh[16];
    int w = threadIdx.x >> 5, ln = threadIdx.x & 31;
    if (ln == 0) { sh[w] = s; sh[w + 8] = sq; }
    __syncthreads();
    if (threadIdx.x < 32) {
        float a  = (threadIdx.x < 8) ? sh[threadIdx.x] : 0.f;
        float b2 = (threadIdx.x < 8) ? sh[threadIdx.x + 8] : 0.f;
        #pragma unroll
        for (int off = 4; off >= 1; off >>= 1) {
            a  += __shfl_xor_sync(0xffffffffu, a,  off);
            b2 += __shfl_xor_sync(0xffffffffu, b2, off);
        }
        if (threadIdx.x == 0) { sh[0] = a; sh[1] = b2; }
    }
    __syncthreads();
    float mu  = sh[0] * (1.f / 1024.f);
    float var = sh[1] * (1.f / 1024.f) - mu * mu;
    float r = rsqrtf(var + 1e-5f);

    float4 gv = *reinterpret_cast<const float4*>(&gam[c]);
    float4 bv = *reinterpret_cast<const float4*>(&bet[c]);
    float4 ov;
    ov.x = (v.x - mu) * r * gv.x + bv.x;
    ov.y = (v.y - mu) * r * gv.y + bv.y;
    ov.z = (v.z - mu) * r * gv.z + bv.z;
    ov.w = (v.w - mu) * r * gv.w + bv.w;
    *reinterpret_cast<float4*>(&out[(size_t)row * DM + c]) = ov;
}

// ---------------- launch ----------------------------------------------------
extern "C" void kernel_launch(void* const* d_in, const int* in_sizes, int n_in,
                              void* d_out, int out_size)
{
    const float* q    = (const float*)d_in[0];
    const float* k    = (const float*)d_in[1];
    const float* v    = (const float*)d_in[2];
    const float* Wq   = (const float*)d_in[3];
    const float* bq   = (const float*)d_in[4];
    const float* Wk   = (const float*)d_in[5];
    const float* bk   = (const float*)d_in[6];
    const float* Wv   = (const float*)d_in[7];
    const float* bv   = (const float*)d_in[8];
    const float* Wo   = (const float*)d_in[9];
    const float* bo   = (const float*)d_in[10];
    const float* ln_g = (const float*)d_in[11];
    const float* ln_b = (const float*)d_in[12];
    float* out = (float*)d_out;

    float *pQ, *pK, *pV, *pX, *pY;
    cudaGetSymbolAddress((void**)&pQ, g_Q);
    cudaGetSymbolAddress((void**)&pK, g_K);
    cudaGetSymbolAddress((void**)&pV, g_V);
    cudaGetSymbolAddress((void**)&pX, g_X);
    cudaGetSymbolAddress((void**)&pY, g_Y);

    const int gemm_smem = 2 * 2 * 128 * GST * 4;                       // 73728 B
    const int attn_smem = (2 * 64 * QST + 64 * VST + 64 * QST) * 4;    // 70656 B
    cudaFuncSetAttribute(gemm_tf32, cudaFuncAttributeMaxDynamicSharedMemorySize, gemm_smem);
    cudaFuncSetAttribute(attn_tc,   cudaFuncAttributeMaxDynamicSharedMemorySize, attn_smem);

    dim3 gg(DM / 128, NR / 128);   // (8, 64)
    gemm_tf32<<<gg, 256, gemm_smem>>>(q, Wq, bq, nullptr, pQ, 0);
    gemm_tf32<<<gg, 256, gemm_smem>>>(k, Wk, bk, nullptr, pK, 0);
    gemm_tf32<<<gg, 256, gemm_smem>>>(v, Wv, bv, nullptr, pV, 0);

    dim3 ga(SS / 64, BB * H_);     // (32, 64)
    attn_tc<<<ga, 128, attn_smem>>>();

    gemm_tf32<<<gg, 256, gemm_smem>>>(pX, Wo, bo, q, pY, 1);

    ln_kernel<<<NR, 256>>>(pY, ln_g, ln_b, out);
}

// round 5
// speedup vs baseline: 7.5991x; 2.1523x over previous
#include <cuda_runtime.h>
#include <cuda_bf16.h>
#include <math.h>
#include <stdint.h>

#define H_ 16
#define DM 1024
#define DK 64
#define BB 4
#define SS 2048
#define NR (BB*SS)   // 8192 rows

// ---------------- scratch (device globals; allocation-free) ----------------
__device__ __nv_bfloat16 gb_q[(size_t)NR*DM];    // bf16 copies of inputs
__device__ __nv_bfloat16 gb_k[(size_t)NR*DM];
__device__ __nv_bfloat16 gb_v[(size_t)NR*DM];
__device__ __nv_bfloat16 gb_Wq[(size_t)DM*DM];
__device__ __nv_bfloat16 gb_Wk[(size_t)DM*DM];
__device__ __nv_bfloat16 gb_Wv[(size_t)DM*DM];
__device__ __nv_bfloat16 gb_Wo[(size_t)DM*DM];
__device__ __nv_bfloat16 g_Qb[(size_t)BB*H_*SS*DK];  // head-major projected Q/K/V
__device__ __nv_bfloat16 g_Kb[(size_t)BB*H_*SS*DK];
__device__ __nv_bfloat16 g_Vb[(size_t)BB*H_*SS*DK];
__device__ __nv_bfloat16 g_Xb[(size_t)NR*DM];        // attention output, flat
__device__ float g_Y[(size_t)NR*DM];                 // pre-LN fp32

// ---------------- helpers ---------------------------------------------------
__device__ __forceinline__ void cp16(uint32_t smem, const void* gmem) {
    asm volatile("cp.async.ca.shared.global [%0], [%1], 16;" :: "r"(smem), "l"(gmem));
}
__device__ __forceinline__ void ldsm4(uint32_t* r, uint32_t a) {
    asm volatile("ldmatrix.sync.aligned.m8n8.x4.shared.b16 {%0,%1,%2,%3}, [%4];"
                 : "=r"(r[0]), "=r"(r[1]), "=r"(r[2]), "=r"(r[3]) : "r"(a));
}
__device__ __forceinline__ void ldsm4t(uint32_t* r, uint32_t a) {
    asm volatile("ldmatrix.sync.aligned.m8n8.x4.trans.shared.b16 {%0,%1,%2,%3}, [%4];"
                 : "=r"(r[0]), "=r"(r[1]), "=r"(r[2]), "=r"(r[3]) : "r"(a));
}
__device__ __forceinline__ void mma_bf16(float* c, const uint32_t* a, uint32_t b0, uint32_t b1) {
    asm volatile(
        "mma.sync.aligned.m16n8k16.row.col.f32.bf16.bf16.f32 "
        "{%0,%1,%2,%3}, {%4,%5,%6,%7}, {%8,%9}, {%0,%1,%2,%3};"
        : "+f"(c[0]), "+f"(c[1]), "+f"(c[2]), "+f"(c[3])
        : "r"(a[0]), "r"(a[1]), "r"(a[2]), "r"(a[3]), "r"(b0), "r"(b1));
}
__device__ __forceinline__ uint32_t pkbf(float a, float b) {
    __nv_bfloat162 h = __floats2bfloat162_rn(a, b);   // .x = a (low), .y = b (high)
    return *reinterpret_cast<uint32_t*>(&h);
}

// ---------------- fp32 -> bf16 conversion -----------------------------------
__global__ __launch_bounds__(256) void cvtk(const float* __restrict__ src,
                                            __nv_bfloat16* __restrict__ dst, int n)
{
    int i = (blockIdx.x * 256 + threadIdx.x) * 4;
    if (i < n) {
        float4 v = *reinterpret_cast<const float4*>(src + i);
        uint2 o;
        o.x = pkbf(v.x, v.y);
        o.y = pkbf(v.z, v.w);
        *reinterpret_cast<uint2*>(dst + i) = o;
    }
}

// ---------------- bf16 GEMM: out = A(8192x1024) @ W(1024x1024)^T + bias -----
// BM=128 BN=128 BK=64, 256 threads, 8 warps (2M x 4N), warp tile 64x32.
// smem rows 128B, XOR chunk swizzle -> conflict-free cp.async + ldmatrix.
// mode 0: head-major bf16 QKV write;  mode 1: fp32 flat write + residual.
__global__ __launch_bounds__(256) void gemm_bf16(
    const __nv_bfloat16* __restrict__ A,
    const __nv_bfloat16* __restrict__ W,
    const float* __restrict__ bias,
    const float* __restrict__ residual,
    void* __restrict__ outv,
    int mode)
{
    extern __shared__ __align__(16) char gsm[];
    const uint32_t sbase = (uint32_t)__cvta_generic_to_shared(gsm);
    const uint32_t sA = sbase;              // [2][128 rows][128 B]
    const uint32_t sB = sbase + 32768;      // [2][128 rows][128 B]

    const int tid = threadIdx.x;
    const int warp = tid >> 5, lane = tid & 31;
    const int wm = warp >> 2, wn = warp & 3;
    const int g = lane >> 2, tg = lane & 3;
    const int lr = lane & 15, lc = lane >> 4;
    const int row0 = blockIdx.y * 128, col0 = blockIdx.x * 128;

    float acc[4][4][4];
    #pragma unroll
    for (int i = 0; i < 4; ++i)
        #pragma unroll
        for (int j = 0; j < 4; ++j)
            #pragma unroll
            for (int r = 0; r < 4; ++r) acc[i][j][r] = 0.f;

    auto issue = [&](int kt, int buf) {
        #pragma unroll
        for (int j = 0; j < 4; ++j) {
            int idx = tid + 256 * j;
            int row = idx >> 3, ch = idx & 7;
            uint32_t off = (uint32_t)(buf * 16384 + row * 128 + ((ch ^ (row & 7)) << 4));
            cp16(sA + off, A + (size_t)(row0 + row) * DM + kt * 64 + ch * 8);
            cp16(sB + off, W + (size_t)(col0 + row) * DM + kt * 64 + ch * 8);
        }
        asm volatile("cp.async.commit_group;");
    };

    issue(0, 0);

    for (int kt = 0; kt < 16; ++kt) {
        int buf = kt & 1;
        asm volatile("cp.async.wait_group 0;");
        __syncthreads();
        if (kt < 15) issue(kt + 1, buf ^ 1);

        uint32_t a0 = sA + buf * 16384, b0 = sB + buf * 16384;

        #pragma unroll
        for (int ks = 0; ks < 4; ++ks) {
            uint32_t af[4][4];
            #pragma unroll
            for (int mi = 0; mi < 4; ++mi) {
                int row = wm * 64 + mi * 16 + lr;
                ldsm4(af[mi], a0 + row * 128 + (((2 * ks + lc) ^ (row & 7)) << 4));
            }
            uint32_t bf[4][2];
            #pragma unroll
            for (int nb = 0; nb < 2; ++nb) {
                int row = wn * 32 + nb * 16 + lr;
                uint32_t r[4];
                ldsm4(r, b0 + row * 128 + (((2 * ks + lc) ^ (row & 7)) << 4));
                bf[2 * nb][0] = r[0]; bf[2 * nb][1] = r[2];
                bf[2 * nb + 1][0] = r[1]; bf[2 * nb + 1][1] = r[3];
            }
            #pragma unroll
            for (int mi = 0; mi < 4; ++mi)
                #pragma unroll
                for (int ni = 0; ni < 4; ++ni)
                    mma_bf16(acc[mi][ni], af[mi], bf[ni][0], bf[ni][1]);
        }
        __syncthreads();
    }

    // epilogue
    #pragma unroll
    for (int mi = 0; mi < 4; ++mi) {
        int r0 = row0 + wm * 64 + mi * 16 + g;
        int r1 = r0 + 8;
        #pragma unroll
        for (int ni = 0; ni < 4; ++ni) {
            int col = col0 + wn * 32 + ni * 8 + 2 * tg;
            float2 bz = *(const float2*)&bias[col];
            const float* c = acc[mi][ni];
            if (mode == 0) {
                __nv_bfloat16* out = (__nv_bfloat16*)outv;
                int h = col >> 6, dk = col & 63;
                int b0_ = r0 >> 11, s0_ = r0 & 2047;
                int b1_ = r1 >> 11, s1_ = r1 & 2047;
                size_t base0 = (((size_t)b0_ * H_ + h) * SS + s0_) * DK + dk;
                size_t base1 = (((size_t)b1_ * H_ + h) * SS + s1_) * DK + dk;
                *reinterpret_cast<uint32_t*>(out + base0) = pkbf(c[0] + bz.x, c[1] + bz.y);
                *reinterpret_cast<uint32_t*>(out + base1) = pkbf(c[2] + bz.x, c[3] + bz.y);
            } else {
                float* out = (float*)outv;
                size_t base0 = (size_t)r0 * DM + col;
                size_t base1 = (size_t)r1 * DM + col;
                float2 rv0 = *(const float2*)&residual[base0];
                float2 rv1 = *(const float2*)&residual[base1];
                *(float2*)&out[base0] = make_float2(c[0] + bz.x + rv0.x, c[1] + bz.y + rv0.y);
                *(float2*)&out[base1] = make_float2(c[2] + bz.x + rv1.x, c[3] + bz.y + rv1.y);
            }
        }
    }
}

// ---------------- bf16 flash attention --------------------------------------
// grid (SS/64, BB*H_), 128 threads (4 warps), warp = 16 q-rows, BKV=64.
// smem: Q[64][128B] + K[2][64][128B] + V[2][64][128B], XOR-swizzled. P in regs.
__global__ __launch_bounds__(128) void attn_bf16()
{
    extern __shared__ __align__(16) char asm_[];
    const uint32_t sbase = (uint32_t)__cvta_generic_to_shared(asm_);
    const uint32_t sQ = sbase;            // 8192 B
    const uint32_t sK = sbase + 8192;     // +buf*8192
    const uint32_t sV = sbase + 24576;    // +buf*8192

    const int bh = blockIdx.y;
    const int b = bh >> 4, h = bh & 15;
    const int q0 = blockIdx.x * 64;
    const int tid = threadIdx.x, warp = tid >> 5, lane = tid & 31;
    const int g = lane >> 2, tg = lane & 3;
    const int lr = lane & 15, lc = lane >> 4;
    const int qm = warp * 16;

    const __nv_bfloat16* Qp = g_Qb + (size_t)bh * SS * DK + (size_t)q0 * DK;
    const __nv_bfloat16* Kp = g_Kb + (size_t)bh * SS * DK;
    const __nv_bfloat16* Vp = g_Vb + (size_t)bh * SS * DK;

    auto issueKV = [&](int kv0, int buf) {
        #pragma unroll
        for (int j = 0; j < 4; ++j) {
            int idx = tid + 128 * j;
            int row = idx >> 3, ch = idx & 7;
            uint32_t off = (uint32_t)(buf * 8192 + row * 128 + ((ch ^ (row & 7)) << 4));
            cp16(sK + off, Kp + (size_t)(kv0 + row) * DK + ch * 8);
            cp16(sV + off, Vp + (size_t)(kv0 + row) * DK + ch * 8);
        }
        asm volatile("cp.async.commit_group;");
    };

    // preload Q + first K/V tile (single group)
    #pragma unroll
    for (int j = 0; j < 4; ++j) {
        int idx = tid + 128 * j;
        int row = idx >> 3, ch = idx & 7;
        cp16(sQ + row * 128 + ((ch ^ (row & 7)) << 4), Qp + (size_t)row * DK + ch * 8);
    }
    issueKV(0, 0);

    float o[8][4];
    #pragma unroll
    for (int i = 0; i < 8; ++i)
        #pragma unroll
        for (int j = 0; j < 4; ++j) o[i][j] = 0.f;
    float m0 = -1e30f, m1 = -1e30f, l0 = 0.f, l1 = 0.f;

    for (int it = 0; it < SS / 64; ++it) {
        int buf = it & 1;
        asm volatile("cp.async.wait_group 0;");
        __syncthreads();
        if (it < SS / 64 - 1) issueKV((it + 1) * 64, buf ^ 1);

        uint32_t kb = sK + buf * 8192, vb = sV + buf * 8192;

        // ---- S = Q @ K^T (16x64 per warp) ----
        float s[8][4];
        #pragma unroll
        for (int i = 0; i < 8; ++i)
            #pragma unroll
            for (int j = 0; j < 4; ++j) s[i][j] = 0.f;

        #pragma unroll
        for (int ks = 0; ks < 4; ++ks) {
            uint32_t af[4];
            {
                int row = qm + lr;
                ldsm4(af, sQ + row * 128 + (((2 * ks + lc) ^ (row & 7)) << 4));
            }
            #pragma unroll
            for (int nb = 0; nb < 4; ++nb) {
                int row = nb * 16 + lr;
                uint32_t r[4];
                ldsm4(r, kb + row * 128 + (((2 * ks + lc) ^ (row & 7)) << 4));
                mma_bf16(s[2 * nb],     af, r[0], r[2]);
                mma_bf16(s[2 * nb + 1], af, r[1], r[3]);
            }
        }

        // ---- online softmax (rows qm+g, qm+g+8) ----
        float mx0 = -1e30f, mx1 = -1e30f;
        #pragma unroll
        for (int nt = 0; nt < 8; ++nt) {
            s[nt][0] *= 0.125f; s[nt][1] *= 0.125f;
            s[nt][2] *= 0.125f; s[nt][3] *= 0.125f;
            mx0 = fmaxf(mx0, fmaxf(s[nt][0], s[nt][1]));
            mx1 = fmaxf(mx1, fmaxf(s[nt][2], s[nt][3]));
        }
        mx0 = fmaxf(mx0, __shfl_xor_sync(0xffffffffu, mx0, 1));
        mx0 = fmaxf(mx0, __shfl_xor_sync(0xffffffffu, mx0, 2));
        mx1 = fmaxf(mx1, __shfl_xor_sync(0xffffffffu, mx1, 1));
        mx1 = fmaxf(mx1, __shfl_xor_sync(0xffffffffu, mx1, 2));

        float nm0 = fmaxf(m0, mx0), nm1 = fmaxf(m1, mx1);
        float a0 = __expf(m0 - nm0), a1 = __expf(m1 - nm1);
        float sum0 = 0.f, sum1 = 0.f;
        uint32_t pk[4][4];
        #pragma unroll
        for (int nt = 0; nt < 8; ++nt) {
            float p0 = __expf(s[nt][0] - nm0);
            float p1 = __expf(s[nt][1] - nm0);
            float p2 = __expf(s[nt][2] - nm1);
            float p3 = __expf(s[nt][3] - nm1);
            sum0 += p0 + p1; sum1 += p2 + p3;
            pk[nt >> 1][(nt & 1) ? 2 : 0] = pkbf(p0, p1);
            pk[nt >> 1][(nt & 1) ? 3 : 1] = pkbf(p2, p3);
        }
        sum0 += __shfl_xor_sync(0xffffffffu, sum0, 1);
        sum0 += __shfl_xor_sync(0xffffffffu, sum0, 2);
        sum1 += __shfl_xor_sync(0xffffffffu, sum1, 1);
        sum1 += __shfl_xor_sync(0xffffffffu, sum1, 2);

        l0 = l0 * a0 + sum0; l1 = l1 * a1 + sum1;
        m0 = nm0; m1 = nm1;
        #pragma unroll
        for (int nt = 0; nt < 8; ++nt) {
            o[nt][0] *= a0; o[nt][1] *= a0;
            o[nt][2] *= a1; o[nt][3] *= a1;
        }

        // ---- O += P @ V (16x64 per warp), P already in A-frag registers ----
        #pragma unroll
        for (int ks = 0; ks < 4; ++ks) {
            #pragma unroll
            for (int nb = 0; nb < 4; ++nb) {
                int row = 16 * ks + lr;
                uint32_t r[4];
                ldsm4t(r, vb + row * 128 + (((2 * nb + lc) ^ (row & 7)) << 4));
                mma_bf16(o[2 * nb],     pk[ks], r[0], r[1]);
                mma_bf16(o[2 * nb + 1], pk[ks], r[2], r[3]);
            }
        }
    }

    // normalize + write flat bf16 X layout (B,S,DM)
    float i0 = 1.f / l0, i1 = 1.f / l1;
    int r0g = q0 + qm + g, r1g = r0g + 8;
    #pragma unroll
    for (int nt = 0; nt < 8; ++nt) {
        int col = h * DK + nt * 8 + 2 * tg;
        size_t b0_ = ((size_t)(b * SS + r0g)) * DM + col;
        size_t b1_ = ((size_t)(b * SS + r1g)) * DM + col;
        *reinterpret_cast<uint32_t*>(g_Xb + b0_) = pkbf(o[nt][0] * i0, o[nt][1] * i0);
        *reinterpret_cast<uint32_t*>(g_Xb + b1_) = pkbf(o[nt][2] * i1, o[nt][3] * i1);
    }
}

// ---------------- LayerNorm over rows of 1024 -------------------------------
__global__ __launch_bounds__(256) void ln_kernel(
    const float* __restrict__ Y,
    const float* __restrict__ gam,
    const float* __restrict__ bet,
    float* __restrict__ out)
{
    int row = blockIdx.x;
    const float* y = Y + (size_t)row * DM;
    int c = threadIdx.x * 4;
    float4 v = *reinterpret_cast<const float4*>(&y[c]);
    float s  = v.x + v.y + v.z + v.w;
    float sq = v.x * v.x + v.y * v.y + v.z * v.z + v.w * v.w;

    #pragma unroll
    for (int off = 16; off >= 1; off >>= 1) {
        s  += __shfl_xor_sync(0xffffffffu, s,  off);
        sq += __shfl_xor_sync(0xffffffffu, sq, off);
    }
    __shared__ float sh[16];
    int w = threadIdx.x >> 5, ln = threadIdx.x & 31;
    if (ln == 0) { sh[w] = s; sh[w + 8] = sq; }
    __syncthreads();
    if (threadIdx.x < 32) {
        float a  = (threadIdx.x < 8) ? sh[threadIdx.x] : 0.f;
        float b2 = (threadIdx.x < 8) ? sh[threadIdx.x + 8] : 0.f;
        #pragma unroll
        for (int off = 4; off >= 1; off >>= 1) {
            a  += __shfl_xor_sync(0xffffffffu, a,  off);
            b2 += __shfl_xor_sync(0xffffffffu, b2, off);
        }
        if (threadIdx.x == 0) { sh[0] = a; sh[1] = b2; }
    }
    __syncthreads();
    float mu  = sh[0] * (1.f / 1024.f);
    float var = sh[1] * (1.f / 1024.f) - mu * mu;
    float r = rsqrtf(var + 1e-5f);

    float4 gv = *reinterpret_cast<const float4*>(&gam[c]);
    float4 bv = *reinterpret_cast<const float4*>(&bet[c]);
    float4 ov;
    ov.x = (v.x - mu) * r * gv.x + bv.x;
    ov.y = (v.y - mu) * r * gv.y + bv.y;
    ov.z = (v.z - mu) * r * gv.z + bv.z;
    ov.w = (v.w - mu) * r * gv.w + bv.w;
    *reinterpret_cast<float4*>(&out[(size_t)row * DM + c]) = ov;
}

// ---------------- launch ----------------------------------------------------
extern "C" void kernel_launch(void* const* d_in, const int* in_sizes, int n_in,
                              void* d_out, int out_size)
{
    const float* q    = (const float*)d_in[0];
    const float* k    = (const float*)d_in[1];
    const float* v    = (const float*)d_in[2];
    const float* Wq   = (const float*)d_in[3];
    const float* bq   = (const float*)d_in[4];
    const float* Wk   = (const float*)d_in[5];
    const float* bk   = (const float*)d_in[6];
    const float* Wv   = (const float*)d_in[7];
    const float* bv   = (const float*)d_in[8];
    const float* Wo   = (const float*)d_in[9];
    const float* bo   = (const float*)d_in[10];
    const float* ln_g = (const float*)d_in[11];
    const float* ln_b = (const float*)d_in[12];
    float* out = (float*)d_out;

    __nv_bfloat16 *pqb, *pkb, *pvb, *pWq, *pWk, *pWv, *pWo, *pQ, *pK, *pV, *pX;
    float *pY;
    cudaGetSymbolAddress((void**)&pqb, gb_q);
    cudaGetSymbolAddress((void**)&pkb, gb_k);
    cudaGetSymbolAddress((void**)&pvb, gb_v);
    cudaGetSymbolAddress((void**)&pWq, gb_Wq);
    cudaGetSymbolAddress((void**)&pWk, gb_Wk);
    cudaGetSymbolAddress((void**)&pWv, gb_Wv);
    cudaGetSymbolAddress((void**)&pWo, gb_Wo);
    cudaGetSymbolAddress((void**)&pQ, g_Qb);
    cudaGetSymbolAddress((void**)&pK, g_Kb);
    cudaGetSymbolAddress((void**)&pV, g_Vb);
    cudaGetSymbolAddress((void**)&pX, g_Xb);
    cudaGetSymbolAddress((void**)&pY, g_Y);

    const int gemm_smem = 65536;
    const int attn_smem = 40960;
    static int s_init = 0;
    if (!s_init) {
        cudaFuncSetAttribute(gemm_bf16, cudaFuncAttributeMaxDynamicSharedMemorySize, gemm_smem);
        cudaFuncSetAttribute(attn_bf16, cudaFuncAttributeMaxDynamicSharedMemorySize, attn_smem);
        s_init = 1;
    }

    // fp32 -> bf16 conversions
    const int NA = NR * DM;     // 8.4M
    const int NW = DM * DM;     // 1.05M
    cvtk<<<NA / 1024, 256>>>(q, pqb, NA);
    cvtk<<<NA / 1024, 256>>>(k, pkb, NA);
    cvtk<<<NA / 1024, 256>>>(v, pvb, NA);
    cvtk<<<NW / 1024, 256>>>(Wq, pWq, NW);
    cvtk<<<NW / 1024, 256>>>(Wk, pWk, NW);
    cvtk<<<NW / 1024, 256>>>(Wv, pWv, NW);
    cvtk<<<NW / 1024, 256>>>(Wo, pWo, NW);

    dim3 gg(DM / 128, NR / 128);   // (8, 64)
    gemm_bf16<<<gg, 256, gemm_smem>>>(pqb, pWq, bq, nullptr, pQ, 0);
    gemm_bf16<<<gg, 256, gemm_smem>>>(pkb, pWk, bk, nullptr, pK, 0);
    gemm_bf16<<<gg, 256, gemm_smem>>>(pvb, pWv, bv, nullptr, pV, 0);

    dim3 ga(SS / 64, BB * H_);     // (32, 64)
    attn_bf16<<<ga, 128, attn_smem>>>();

    gemm_bf16<<<gg, 256, gemm_smem>>>(pX, pWo, bo, q, pY, 1);

    ln_kernel<<<NR, 256>>>(pY, ln_g, ln_b, out);
}